// round 8
// baseline (speedup 1.0000x reference)
#include <cuda_runtime.h>
#include <math.h>

#define KB 10
#define VV 50257
#define EE 128
#define H1D 128
#define H2D 64
#define QQ 64
#define TENC 2048
#define MAXLEN 30
#define SOSTOK 1
#define EOSTOK 2
#define GRID 148
#define RPB 340            // 148*340 = 50320 >= 50257
#define HRPB (RPB-256)     // 84
#define NCHUNK 16
#define CHUNK 128
#define NUNITS (KB*NCHUNK) // 160
#define SEQW (MAXLEN + 1)  // 31
#define TPB 12             // candidates kept per (beam, block)
#define NCAND (GRID*KB*TPB)

// ---------------- persistent device state ----------------
__device__ float g_h1[KB*H1D], g_c1[KB*H1D], g_h2[KB*H2D], g_c2[KB*H2D], g_ctx[KB*QQ];
__device__ float g_h1n[KB*H1D], g_c1n[KB*H1D], g_h2n[KB*H2D], g_c2n[KB*H2D], g_ctxn[KB*QQ];
__device__ float g_scores[KB];
__device__ int   g_prev[KB], g_fin[KB], g_seqs[KB*SEQW];
__device__ float g_attM[KB*NCHUNK], g_attA[KB*NCHUNK], g_attB[KB*NCHUNK];
__device__ float g_attC[KB*NCHUNK*QQ];
__device__ double g_sump[GRID*KB];
__device__ float g_cand_val[NCAND];
__device__ int   g_cand_idx[NCAND];
__device__ unsigned g_count = 0;
__device__ unsigned g_epoch = 0;

// order-preserving float -> u32 key (larger key == larger float)
__device__ __forceinline__ unsigned ordkey(float f){
  unsigned u = __float_as_uint(f);
  return (u & 0x80000000u) ? ~u : (u | 0x80000000u);
}
__device__ __forceinline__ float unordkey(unsigned k){
  unsigned u = (k & 0x80000000u) ? (k & 0x7FFFFFFFu) : ~k;
  return __uint_as_float(u);
}
// packed 2xfp32 FMA
__device__ __forceinline__ void ffma2(unsigned long long& d, unsigned long long a, unsigned long long b){
  asm("fma.rn.f32x2 %0, %1, %2, %0;" : "+l"(d) : "l"(a), "l"(b));
}
// compensated fp32 FMA accumulate: true value ~= s - c
__device__ __forceinline__ void kfma(float& s, float& c, float a, float b){
  float p  = __fmul_rn(a, b);
  float e  = __fmaf_rn(a, b, -p);
  float y  = p - c;
  float t2 = s + y;
  c = (t2 - s) - y;
  s = t2;
  c -= e;
}

// ---------------- hand-rolled grid barrier (all 148 blocks co-resident) ----------------
__device__ __forceinline__ void gridbar(unsigned& ep){
  __syncthreads();
  if (threadIdx.x==0){
    __threadfence();                       // release: make this block's writes visible
    unsigned prev = atomicAdd(&g_count, 1u);
    if (prev == GRID-1u){
      g_count = 0u;                        // reset for next barrier
      __threadfence();                     // order reset before epoch bump
      atomicAdd(&g_epoch, 1u);             // release waiters
    } else {
      volatile unsigned* e = &g_epoch;
      while ((int)(*e - ep) < 1) { }
    }
    __threadfence();                       // acquire side: CCTL.IVALL flushes L1D
  }
  __syncthreads();
  ep++;
}

// ---------------- shared-memory phase overlays ----------------
struct SM_L1 { float sx[KB*192]; float sh[KB*H1D]; double sg[4*KB]; double snl[4*KB]; };
struct SM_L2 { float sx[KB*H1D]; float sh[KB*H2D]; double sg[4*KB]; double snl[4*KB]; };
struct SM_AT { float h2s[H2D]; float qp[4][QQ]; float qs[QQ]; float ws[CHUNK];
               float redm[4]; float redab[4][2]; float cs4[4][QQ]; };
struct SM_LO { float xs[KB*128]; float lg[KB][RPB]; float wred[8][KB];
               float sM[KB]; float scf[KB][NCHUNK]; double sA[KB]; double sB[KB]; };
struct SM_SE { double sp[256]; unsigned long long skeys[256*10]; unsigned long long wmax[8];
               unsigned long long swin; unsigned long long topk[KB];
               float slse[KB]; float sscore[KB]; float sval[KB];
               int sfin[KB]; int spb[KB]; int stok[KB]; int sseq[KB*SEQW]; };
#define SMRAW_BYTES 24576

__global__ void __launch_bounds__(256) mega_kernel(
  const float* __restrict__ enc_key, const float* __restrict__ enc_val,
  const float* __restrict__ mask,    const float* __restrict__ emb,
  const float* __restrict__ Wih1, const float* __restrict__ Whh1,
  const float* __restrict__ bih1, const float* __restrict__ bhh1,
  const float* __restrict__ Wih2, const float* __restrict__ Whh2,
  const float* __restrict__ bih2, const float* __restrict__ bhh2,
  const float* __restrict__ Wq, const float* __restrict__ bq,
  const float* __restrict__ Wc, const float* __restrict__ bc,
  float* __restrict__ out)
{
  __shared__ __align__(16) char smraw[SMRAW_BYTES];
  __shared__ unsigned s_ep0;
  int t = threadIdx.x, bid = blockIdx.x;
  int lane = t & 31, wid = t >> 5;

  if (t==0){
    volatile unsigned* e = &g_epoch;
    s_ep0 = *e;
  }
  __syncthreads();
  unsigned ep = s_ep0;

  // ---------- init (block 0) ----------
  if (bid==0){
    for (int i=t;i<KB*H1D;i+=256){ g_h1[i]=0.f; g_c1[i]=0.f; }
    for (int i=t;i<KB*H2D;i+=256){ g_h2[i]=0.f; g_c2[i]=0.f; }
    for (int i=t;i<KB*QQ;i+=256)  g_ctx[i]=0.f;
    for (int i=t;i<KB*SEQW;i+=256) g_seqs[i]=SOSTOK;
    if (t<KB){ g_scores[t]=0.f; g_prev[t]=SOSTOK; g_fin[t]=0; }
  }
  gridbar(ep);

  for (int step=0; step<MAXLEN; step++){

    // ---------- LSTM1: blocks 0..127 ----------
    if (bid < H1D){
      SM_L1* s1 = (SM_L1*)smraw;
      int n = bid;
      for (int i=t;i<KB*192;i+=256){
        int b=i/192, j=i%192;
        s1->sx[i] = (j<EE) ? emb[(size_t)g_prev[b]*EE + j] : g_ctx[b*QQ + (j-EE)];
      }
      for (int i=t;i<KB*H1D;i+=256) s1->sh[i] = g_h1[i];
      __syncthreads();
      if (t < 128){
        int g = t>>5, ln = t&31;
        const float* wi = Wih1 + (size_t)(g*H1D+n)*192;
        const float* wh = Whh1 + (size_t)(g*H1D+n)*H1D;
        float s[KB], c[KB];
        #pragma unroll
        for (int b=0;b<KB;b++){ s[b]=0.f; c[b]=0.f; }
        for (int j=ln;j<192;j+=32){
          float w = wi[j];
          #pragma unroll
          for (int b=0;b<KB;b++) kfma(s[b], c[b], w, s1->sx[b*192+j]);
        }
        for (int j=ln;j<H1D;j+=32){
          float w = wh[j];
          #pragma unroll
          for (int b=0;b<KB;b++) kfma(s[b], c[b], w, s1->sh[b*H1D+j]);
        }
        double bb = (double)bih1[g*H1D+n] + (double)bhh1[g*H1D+n];
        #pragma unroll
        for (int b=0;b<KB;b++){
          float ss=s[b], cc=c[b];
          for (int o=16;o>0;o>>=1){
            ss += __shfl_down_sync(0xffffffffu, ss, o);
            cc += __shfl_down_sync(0xffffffffu, cc, o);
          }
          if (ln==0) s1->sg[g*KB+b] = ((double)ss - (double)cc) + bb;
        }
      }
      __syncthreads();
      if (t<4*KB){
        int gg=t/KB;
        double v = s1->sg[t];
        s1->snl[t] = (gg==2) ? tanh(v) : 1.0/(1.0+exp(-v));
      }
      __syncthreads();
      if (t<KB){
        double cd = s1->snl[1*KB+t]*(double)g_c1[t*H1D+n] + s1->snl[0*KB+t]*s1->snl[2*KB+t];
        float cf = (float)cd;
        g_c1n[t*H1D+n] = cf;
        g_h1n[t*H1D+n] = (float)(s1->snl[3*KB+t]*tanh((double)cf));
      }
    }
    gridbar(ep);

    // ---------- LSTM2: blocks 0..63 ----------
    if (bid < H2D){
      SM_L2* s2 = (SM_L2*)smraw;
      int n = bid;
      for (int i=t;i<KB*H1D;i+=256) s2->sx[i] = g_h1n[i];
      for (int i=t;i<KB*H2D;i+=256) s2->sh[i] = g_h2[i];
      __syncthreads();
      if (t < 128){
        int g = t>>5, ln = t&31;
        const float* wi = Wih2 + (size_t)(g*H2D+n)*H1D;
        const float* wh = Whh2 + (size_t)(g*H2D+n)*H2D;
        float s[KB], c[KB];
        #pragma unroll
        for (int b=0;b<KB;b++){ s[b]=0.f; c[b]=0.f; }
        for (int j=ln;j<H1D;j+=32){
          float w = wi[j];
          #pragma unroll
          for (int b=0;b<KB;b++) kfma(s[b], c[b], w, s2->sx[b*H1D+j]);
        }
        for (int j=ln;j<H2D;j+=32){
          float w = wh[j];
          #pragma unroll
          for (int b=0;b<KB;b++) kfma(s[b], c[b], w, s2->sh[b*H2D+j]);
        }
        double bb = (double)bih2[g*H2D+n] + (double)bhh2[g*H2D+n];
        #pragma unroll
        for (int b=0;b<KB;b++){
          float ss=s[b], cc=c[b];
          for (int o=16;o>0;o>>=1){
            ss += __shfl_down_sync(0xffffffffu, ss, o);
            cc += __shfl_down_sync(0xffffffffu, cc, o);
          }
          if (ln==0) s2->sg[g*KB+b] = ((double)ss - (double)cc) + bb;
        }
      }
      __syncthreads();
      if (t<4*KB){
        int gg=t/KB;
        double v = s2->sg[t];
        s2->snl[t] = (gg==2) ? tanh(v) : 1.0/(1.0+exp(-v));
      }
      __syncthreads();
      if (t<KB){
        double cd = s2->snl[1*KB+t]*(double)g_c2[t*H2D+n] + s2->snl[0*KB+t]*s2->snl[2*KB+t];
        float cf = (float)cd;
        g_c2n[t*H2D+n] = cf;
        g_h2n[t*H2D+n] = (float)(s2->snl[3*KB+t]*tanh((double)cf));
      }
    }
    gridbar(ep);

    // ---------- attention partials: 160 units over 148 blocks ----------
    for (int u=bid; u<NUNITS; u+=GRID){
      SM_AT* sa = (SM_AT*)smraw;
      int beam = u>>4, ch = u&15;
      __syncthreads();
      if (t<H2D) sa->h2s[t] = g_h2n[beam*H2D+t];
      __syncthreads();
      {
        int qi = t&63, part = t>>6;
        const float* w = Wq + qi*H2D + part*16;
        float s=0.f, c=0.f;
        #pragma unroll
        for (int j=0;j<16;j++) kfma(s, c, w[j], sa->h2s[part*16+j]);
        sa->qp[part][qi] = s - c;
      }
      __syncthreads();
      if (t<QQ) sa->qs[t] = bq[t] + ((sa->qp[0][t]+sa->qp[1][t])+(sa->qp[2][t]+sa->qp[3][t]));
      __syncthreads();
      int tok = ch*CHUNK + (t&127);
      float e = -1e30f;
      if (t<128){
        const float4* kr = (const float4*)(enc_key + (size_t)tok*QQ);
        const float4* q4 = (const float4*)sa->qs;
        float s0=0,c0=0,s1=0,c1=0,s2=0,c2=0,s3=0,c3=0;
        #pragma unroll
        for (int j=0;j<16;j++){
          float4 kv = kr[j];
          float4 qv = q4[j];
          kfma(s0,c0,qv.x,kv.x);
          kfma(s1,c1,qv.y,kv.y);
          kfma(s2,c2,qv.z,kv.z);
          kfma(s3,c3,qv.w,kv.w);
        }
        e = ((s0-c0)+(s1-c1))+((s2-c2)+(s3-c3));
      }
      float m = e;
      for (int o=16;o>0;o>>=1) m = fmaxf(m, __shfl_down_sync(0xffffffffu, m, o));
      if (lane==0 && wid<4) sa->redm[wid]=m;
      __syncthreads();
      float M = fmaxf(fmaxf(sa->redm[0],sa->redm[1]),fmaxf(sa->redm[2],sa->redm[3]));
      float wexp=0.f, wmask=0.f;
      if (t<128){
        wexp = expf(e-M);
        wmask = wexp*mask[tok];
        sa->ws[t] = wmask;
      }
      float a=wexp, b2=wmask;
      for (int o=16;o>0;o>>=1){
        a  += __shfl_down_sync(0xffffffffu, a, o);
        b2 += __shfl_down_sync(0xffffffffu, b2, o);
      }
      if (lane==0 && wid<4){ sa->redab[wid][0]=a; sa->redab[wid][1]=b2; }
      __syncthreads();
      {
        int v = t&63, grp = t>>6;
        const float* vb = enc_val + (size_t)(ch*CHUNK + grp*32)*QQ + v;
        float s0=0,c0=0,s1=0,c1=0;
        #pragma unroll 4
        for (int tl=0; tl<32; tl+=2){
          kfma(s0,c0, sa->ws[grp*32+tl],   vb[(size_t)tl*QQ]);
          kfma(s1,c1, sa->ws[grp*32+tl+1], vb[(size_t)(tl+1)*QQ]);
        }
        sa->cs4[grp][v] = (s0-c0)+(s1-c1);
      }
      __syncthreads();
      if (t<QQ) g_attC[(beam*NCHUNK+ch)*QQ + t] = (sa->cs4[0][t]+sa->cs4[1][t])+(sa->cs4[2][t]+sa->cs4[3][t]);
      if (t==0){
        g_attM[beam*NCHUNK+ch]=M;
        g_attA[beam*NCHUNK+ch]=(sa->redab[0][0]+sa->redab[1][0])+(sa->redab[2][0]+sa->redab[3][0]);
        g_attB[beam*NCHUNK+ch]=(sa->redab[0][1]+sa->redab[1][1])+(sa->redab[2][1]+sa->redab[3][1]);
      }
    }
    gridbar(ep);

    // ---------- logits (+merge prologue): all 148 blocks ----------
    {
      SM_LO* so = (SM_LO*)smraw;
      if (t<KB){
        float M=-1e30f;
        #pragma unroll
        for (int c=0;c<NCHUNK;c++) M = fmaxf(M, g_attM[t*NCHUNK+c]);
        so->sM[t]=M;
      }
      __syncthreads();
      if (t<KB*NCHUNK){
        int b=t/NCHUNK;
        so->scf[b][t%NCHUNK] = expf(g_attM[t]-so->sM[b]);
      }
      __syncthreads();
      if (t<KB){
        double A=0.0, B=0.0;
        #pragma unroll
        for (int c=0;c<NCHUNK;c++){
          A += (double)g_attA[t*NCHUNK+c]*(double)so->scf[t][c];
          B += (double)g_attB[t*NCHUNK+c]*(double)so->scf[t][c];
        }
        so->sA[t]=A; so->sB[t]=B;
      }
      __syncthreads();
      for (int i=t;i<KB*128;i+=256){
        int b=i>>7, j=i&127;
        float x;
        if (j < H2D) x = g_h2n[b*H2D+j];
        else {
          int v = j - H2D;
          float s=0.f, c=0.f;
          #pragma unroll
          for (int cc=0;cc<NCHUNK;cc++) kfma(s, c, g_attC[(b*NCHUNK+cc)*QQ+v], so->scf[b][cc]);
          double Cd = (double)s - (double)c;
          x = (float)((Cd/so->sA[b]) / fmax(so->sB[b]/so->sA[b], 2e-30));
          if (bid == 0) g_ctxn[b*QQ+v] = x;
        }
        so->xs[i] = x;
      }
      __syncthreads();
      int v0 = bid*RPB + t;
      int v1 = v0 + 256;
      bool ok0 = v0 < VV;
      bool ok1 = (t < HRPB) && (v1 < VV);
      const ulonglong2* wr0 = (const ulonglong2*)(Wc + (size_t)(ok0?v0:0)*128);
      const ulonglong2* wr1 = (const ulonglong2*)(Wc + (size_t)(ok1?v1:0)*128);
      const ulonglong2* xp = (const ulonglong2*)so->xs;
      unsigned long long a0[KB], a1[KB];
      #pragma unroll
      for (int b=0;b<KB;b++){ a0[b]=0ull; a1[b]=0ull; }
      #pragma unroll 2
      for (int j=0;j<32;j++){
        ulonglong2 w0 = wr0[j];
        ulonglong2 w1 = wr1[j];
        #pragma unroll
        for (int b=0;b<KB;b++){
          ulonglong2 xv = xp[b*32+j];
          ffma2(a0[b], w0.x, xv.x);
          ffma2(a0[b], w0.y, xv.y);
          ffma2(a1[b], w1.x, xv.x);
          ffma2(a1[b], w1.y, xv.y);
        }
      }
      float bc0 = ok0 ? bc[v0] : 0.f;
      float bc1 = ok1 ? bc[v1] : 0.f;
      float ex[KB];
      #pragma unroll
      for (int b=0;b<KB;b++){
        float lo0 = __uint_as_float((unsigned)(a0[b] & 0xffffffffu));
        float hi0 = __uint_as_float((unsigned)(a0[b] >> 32));
        float lo1 = __uint_as_float((unsigned)(a1[b] & 0xffffffffu));
        float hi1 = __uint_as_float((unsigned)(a1[b] >> 32));
        float l0 = ok0 ? (lo0 + hi0) + bc0 : -1e30f;
        float l1 = ok1 ? (lo1 + hi1) + bc1 : -1e30f;
        so->lg[b][t] = l0;
        if (t < HRPB) so->lg[b][t+256] = l1;
        ex[b] = expf(l0) + expf(l1);
      }
      #pragma unroll
      for (int b=0;b<KB;b++){
        float s = ex[b];
        for (int o=16;o>0;o>>=1) s += __shfl_down_sync(0xffffffffu, s, o);
        if (lane==0) so->wred[wid][b] = s;
      }
      __syncthreads();
      if (t<KB){
        double s=0.0;
        for (int w=0;w<8;w++) s += (double)so->wred[w][t];
        g_sump[bid*KB+t] = s;
      }
      for (int bm=wid; bm<KB; bm+=8){
        for (int j=0;j<TPB;j++){
          unsigned long long best=0ull;
          for (int r2=lane; r2<RPB; r2+=32){
            unsigned long long k = ((unsigned long long)ordkey(so->lg[bm][r2])<<32) | (unsigned)(~(unsigned)r2);
            if (k>best) best=k;
          }
          for (int o=16;o>0;o>>=1){
            unsigned long long ok = __shfl_down_sync(0xffffffffu, best, o);
            if (ok>best) best=ok;
          }
          best = __shfl_sync(0xffffffffu, best, 0);
          int rs = (int)(~(unsigned)(best & 0xffffffffu));
          if (lane==0){
            g_cand_val[(bid*KB+bm)*TPB+j] = so->lg[bm][rs];
            g_cand_idx[(bid*KB+bm)*TPB+j] = bid*RPB + rs;
            so->lg[bm][rs] = -1e30f;
          }
          __syncwarp();
        }
      }
    }
    gridbar(ep);

    // ---------- select: block 0 ----------
    if (bid==0){
      SM_SE* se = (SM_SE*)smraw;
      {
        double s=0.0;
        if (t < 250){
          int b = t/25, part = t%25;
          for (int b2=part; b2<GRID; b2+=25) s += g_sump[b2*KB+b];
        }
        se->sp[t]=s;
      }
      __syncthreads();
      if (t<KB){
        double s=0.0;
        for (int q=0;q<25;q++) s += se->sp[t*25+q];
        se->slse[t] = (float)log(s);
        se->sscore[t] = g_scores[t];
        se->sfin[t] = g_fin[t];
      }
      __syncthreads();
      unsigned long long list[10];
      #pragma unroll
      for (int j=0;j<10;j++) list[j]=0ull;
      for (int c=t;c<NCAND;c+=256){
        int b = (c/TPB)%KB;
        if (se->sfin[b]) continue;
        if (step==0 && b>0) continue;
        float logp = g_cand_val[c] - se->slse[b];
        float v = se->sscore[b] + logp;
        int flat = b*VV + g_cand_idx[c];
        unsigned long long k = ((unsigned long long)ordkey(v)<<32) | (unsigned)(~(unsigned)flat);
        if (k > list[9]){
          list[9]=k;
          for (int j=8;j>=0;j--){
            if (list[j] < list[j+1]){ unsigned long long tmp=list[j]; list[j]=list[j+1]; list[j+1]=tmp; }
            else break;
          }
        }
      }
      if (t<KB && se->sfin[t]){
        float v = se->sscore[t];
        int flat = t*VV + EOSTOK;
        unsigned long long k = ((unsigned long long)ordkey(v)<<32) | (unsigned)(~(unsigned)flat);
        if (k > list[9]){
          list[9]=k;
          for (int j=8;j>=0;j--){
            if (list[j] < list[j+1]){ unsigned long long tmp=list[j]; list[j]=list[j+1]; list[j+1]=tmp; }
            else break;
          }
        }
      }
      #pragma unroll
      for (int j=0;j<10;j++) se->skeys[t*10+j]=list[j];
      __syncthreads();
      for (int j=0;j<10;j++){
        unsigned long long m=0ull;
        #pragma unroll
        for (int q=0;q<10;q++){ unsigned long long k=se->skeys[t*10+q]; if (k>m) m=k; }
        for (int o=16;o>0;o>>=1){
          unsigned long long ok = __shfl_down_sync(0xffffffffu, m, o);
          if (ok>m) m=ok;
        }
        if (lane==0) se->wmax[wid]=m;
        __syncthreads();
        if (t==0){
          unsigned long long w=se->wmax[0];
          for (int q=1;q<8;q++) if (se->wmax[q]>w) w=se->wmax[q];
          se->swin=w; se->topk[j]=w;
        }
        __syncthreads();
        unsigned long long win = se->swin;
        #pragma unroll
        for (int q=0;q<10;q++) if (se->skeys[t*10+q]==win) se->skeys[t*10+q]=0ull;
        __syncthreads();
      }
      if (t<KB){
        unsigned long long k = se->topk[t];
        se->sval[t] = unordkey((unsigned)(k>>32));
        int flat = (int)(~(unsigned)(k & 0xffffffffu));
        se->spb[t]  = flat / VV;
        se->stok[t] = flat % VV;
      }
      for (int i=t;i<KB*SEQW;i+=256) se->sseq[i] = g_seqs[i];
      __syncthreads();
      for (int i=t;i<KB*H1D;i+=256){
        int nb=i>>7, u=i&127;
        g_h1[i]=g_h1n[se->spb[nb]*H1D+u];
        g_c1[i]=g_c1n[se->spb[nb]*H1D+u];
      }
      for (int i=t;i<KB*H2D;i+=256){
        int nb=i>>6, u=i&63;
        g_h2[i]=g_h2n[se->spb[nb]*H2D+u];
        g_c2[i]=g_c2n[se->spb[nb]*H2D+u];
        g_ctx[i]=g_ctxn[se->spb[nb]*QQ+u];
      }
      for (int i=t;i<KB*SEQW;i+=256){
        int nb=i/SEQW, cc=i%SEQW;
        g_seqs[i] = se->sseq[se->spb[nb]*SEQW+cc];
      }
      __syncthreads();
      if (t<KB){
        g_seqs[t*SEQW + step + 1] = se->stok[t];
        g_prev[t]   = se->stok[t];
        g_scores[t] = se->sval[t];
        g_fin[t]    = se->sfin[se->spb[t]] | (se->stok[t]==EOSTOK);
      }
    }
    gridbar(ep);
  }

  // ---------- finalize: block 0 ----------
  if (bid==0){
    SM_SE* se = (SM_SE*)smraw;
    if (t<KB){
      int first=-1;
      for (int c=1;c<=MAXLEN;c++){
        if (g_seqs[t*SEQW+c]==EOSTOK){ first=c-1; break; }
      }
      float len = (first>=0) ? (float)(first+2) : (float)(MAXLEN+2);
      se->sval[t] = (float)((double)g_scores[t] / pow((double)len, 1.2));
    }
    __syncthreads();
    for (int i=t;i<KB*SEQW;i+=256) out[i] = (float)g_seqs[i];
    if (t<KB){
      out[KB*SEQW + t]       = g_scores[t];
      out[KB*SEQW + KB + t]  = se->sval[t];
    }
  }
}

extern "C" void kernel_launch(void* const* d_in, const int* in_sizes, int n_in,
                              void* d_out, int out_size){
  const float* enc_key = (const float*)d_in[0];
  const float* enc_val = (const float*)d_in[1];
  const float* mask    = (const float*)d_in[2];
  const float* emb     = (const float*)d_in[3];
  const float* Wih1    = (const float*)d_in[4];
  const float* Whh1    = (const float*)d_in[5];
  const float* bih1    = (const float*)d_in[6];
  const float* bhh1    = (const float*)d_in[7];
  const float* Wih2    = (const float*)d_in[8];
  const float* Whh2    = (const float*)d_in[9];
  const float* bih2    = (const float*)d_in[10];
  const float* bhh2    = (const float*)d_in[11];
  const float* Wq      = (const float*)d_in[12];
  const float* bq      = (const float*)d_in[13];
  const float* Wc      = (const float*)d_in[14];
  const float* bc      = (const float*)d_in[15];

  mega_kernel<<<GRID,256>>>(enc_key, enc_val, mask, emb,
                            Wih1, Whh1, bih1, bhh1,
                            Wih2, Whh2, bih2, bhh2,
                            Wq, bq, Wc, bc, (float*)d_out);
}

// round 9
// speedup vs baseline: 1.1576x; 1.1576x over previous
#include <cuda_runtime.h>
#include <math.h>

#define KB 10
#define VV 50257
#define EE 128
#define H1D 128
#define H2D 64
#define QQ 64
#define TENC 2048
#define MAXLEN 30
#define SOSTOK 1
#define EOSTOK 2
#define GRID 148
#define NTHR 512
#define RPB 340            // 148*340 = 50320 >= 50257
#define LROWS 170          // threads doing 2 rows each
#define NCHUNK 8
#define CHUNK 256
#define NUNITS (KB*NCHUNK) // 80
#define SEQW (MAXLEN + 1)  // 31
#define TPB 12
#define NCAND (GRID*KB*TPB)

// ---------------- persistent device state ----------------
__device__ float g_h1[KB*H1D], g_c1[KB*H1D], g_h2[KB*H2D], g_c2[KB*H2D], g_ctx[KB*QQ];
__device__ float g_h1n[KB*H1D], g_c1n[KB*H1D], g_h2n[KB*H2D], g_c2n[KB*H2D], g_ctxn[KB*QQ];
__device__ float g_scores[KB];
__device__ int   g_prev[KB], g_fin[KB], g_seqs[KB*SEQW];
__device__ float g_attM[KB*NCHUNK], g_attA[KB*NCHUNK], g_attB[KB*NCHUNK];
__device__ float g_attC[KB*NCHUNK*QQ];
__device__ double g_sump[GRID*KB];
__device__ float g_cand_val[NCAND];
__device__ int   g_cand_idx[NCAND];
__device__ unsigned g_count = 0;
__device__ unsigned g_epoch = 0;

__device__ __forceinline__ unsigned ordkey(float f){
  unsigned u = __float_as_uint(f);
  return (u & 0x80000000u) ? ~u : (u | 0x80000000u);
}
__device__ __forceinline__ float unordkey(unsigned k){
  unsigned u = (k & 0x80000000u) ? (k & 0x7FFFFFFFu) : ~k;
  return __uint_as_float(u);
}
__device__ __forceinline__ void ffma2(unsigned long long& d, unsigned long long a, unsigned long long b){
  asm("fma.rn.f32x2 %0, %1, %2, %0;" : "+l"(d) : "l"(a), "l"(b));
}
// compensated fp32 FMA accumulate: true value ~= s - c
__device__ __forceinline__ void kfma(float& s, float& c, float a, float b){
  float p  = __fmul_rn(a, b);
  float e  = __fmaf_rn(a, b, -p);
  float y  = p - c;
  float t2 = s + y;
  c = (t2 - s) - y;
  s = t2;
  c -= e;
}

// ---------------- grid barrier with backoff ----------------
__device__ __forceinline__ void gridbar(unsigned& ep){
  __syncthreads();
  if (threadIdx.x==0){
    __threadfence();
    unsigned prev = atomicAdd(&g_count, 1u);
    if (prev == GRID-1u){
      g_count = 0u;
      __threadfence();
      atomicAdd(&g_epoch, 1u);
    } else {
      volatile unsigned* e = &g_epoch;
      while ((int)(*e - ep) < 1) __nanosleep(64);
    }
    __threadfence();   // invalidate L1 so cross-block data is fresh
  }
  __syncthreads();
  ep++;
}

// ---------------- shared-memory phase overlays ----------------
struct SM_L1 { float sx[KB*192]; float sh[KB*H1D]; double sg[4*KB]; double snl[4*KB]; };
struct SM_L2 { float sx[KB*H1D]; float sh[KB*H2D]; double sg[4*KB]; double snl[4*KB]; };
struct SM_AT { float h2s[H2D]; float qp[4][QQ]; float qs[QQ]; float ws[CHUNK];
               float redm[8]; float redab[8][2]; float cs[8][QQ]; };
struct SM_LO { float xs[KB*128]; float lg[KB][RPB]; float wred[16][KB];
               float sM[KB]; float scf[KB][NCHUNK]; double sA[KB]; double sB[KB]; };
struct SM_SE { double sp[256]; unsigned long long skeys[256*10]; unsigned long long wmax[16];
               unsigned long long swin; unsigned long long topk[KB];
               float slse[KB]; float sscore[KB]; float sval[KB];
               int sfin[KB]; int spb[KB]; int stok[KB]; int sseq[KB*SEQW]; };
#define SMRAW_BYTES 25600

__global__ void __launch_bounds__(NTHR) mega_kernel(
  const float* __restrict__ enc_key, const float* __restrict__ enc_val,
  const float* __restrict__ mask,    const float* __restrict__ emb,
  const float* __restrict__ Wih1, const float* __restrict__ Whh1,
  const float* __restrict__ bih1, const float* __restrict__ bhh1,
  const float* __restrict__ Wih2, const float* __restrict__ Whh2,
  const float* __restrict__ bih2, const float* __restrict__ bhh2,
  const float* __restrict__ Wq, const float* __restrict__ bq,
  const float* __restrict__ Wc, const float* __restrict__ bc,
  float* __restrict__ out)
{
  __shared__ __align__(16) char smraw[SMRAW_BYTES];
  __shared__ unsigned s_ep0;
  int t = threadIdx.x, bid = blockIdx.x;
  int lane = t & 31, wid = t >> 5;

  if (t==0){
    volatile unsigned* e = &g_epoch;
    s_ep0 = *e;
  }
  __syncthreads();
  unsigned ep = s_ep0;

  if (bid==0){
    for (int i=t;i<KB*H1D;i+=NTHR){ g_h1[i]=0.f; g_c1[i]=0.f; }
    for (int i=t;i<KB*H2D;i+=NTHR){ g_h2[i]=0.f; g_c2[i]=0.f; }
    for (int i=t;i<KB*QQ;i+=NTHR)  g_ctx[i]=0.f;
    for (int i=t;i<KB*SEQW;i+=NTHR) g_seqs[i]=SOSTOK;
    if (t<KB){ g_scores[t]=0.f; g_prev[t]=SOSTOK; g_fin[t]=0; }
  }
  gridbar(ep);

  for (int step=0; step<MAXLEN; step++){

    // ---------- LSTM1: blocks 0..127 ----------
    if (bid < H1D){
      SM_L1* s1 = (SM_L1*)smraw;
      int n = bid;
      for (int i=t;i<KB*192;i+=NTHR){
        int b=i/192, j=i%192;
        s1->sx[i] = (j<EE) ? emb[(size_t)g_prev[b]*EE + j] : g_ctx[b*QQ + (j-EE)];
      }
      for (int i=t;i<KB*H1D;i+=NTHR) s1->sh[i] = g_h1[i];
      __syncthreads();
      if (t < 128){
        int g = t>>5, ln = t&31;
        const float* wi = Wih1 + (size_t)(g*H1D+n)*192;
        const float* wh = Whh1 + (size_t)(g*H1D+n)*H1D;
        float s[KB], c[KB];
        #pragma unroll
        for (int b=0;b<KB;b++){ s[b]=0.f; c[b]=0.f; }
        #pragma unroll 2
        for (int j=ln;j<192;j+=32){
          float w = wi[j];
          #pragma unroll
          for (int b=0;b<KB;b++) kfma(s[b], c[b], w, s1->sx[b*192+j]);
        }
        #pragma unroll 2
        for (int j=ln;j<H1D;j+=32){
          float w = wh[j];
          #pragma unroll
          for (int b=0;b<KB;b++) kfma(s[b], c[b], w, s1->sh[b*H1D+j]);
        }
        double bb = (double)bih1[g*H1D+n] + (double)bhh1[g*H1D+n];
        #pragma unroll
        for (int b=0;b<KB;b++){
          float ss=s[b], cc=c[b];
          for (int o=16;o>0;o>>=1){
            ss += __shfl_down_sync(0xffffffffu, ss, o);
            cc += __shfl_down_sync(0xffffffffu, cc, o);
          }
          if (ln==0) s1->sg[g*KB+b] = ((double)ss - (double)cc) + bb;
        }
      }
      __syncthreads();
      if (t<4*KB){
        int gg=t/KB;
        double v = s1->sg[t];
        s1->snl[t] = (gg==2) ? tanh(v) : 1.0/(1.0+exp(-v));
      }
      __syncthreads();
      if (t<KB){
        double cd = s1->snl[1*KB+t]*(double)g_c1[t*H1D+n] + s1->snl[0*KB+t]*s1->snl[2*KB+t];
        float cf = (float)cd;
        g_c1n[t*H1D+n] = cf;
        g_h1n[t*H1D+n] = (float)(s1->snl[3*KB+t]*tanh((double)cf));
      }
    }
    gridbar(ep);

    // ---------- LSTM2: blocks 0..63 ----------
    if (bid < H2D){
      SM_L2* s2 = (SM_L2*)smraw;
      int n = bid;
      for (int i=t;i<KB*H1D;i+=NTHR) s2->sx[i] = g_h1n[i];
      for (int i=t;i<KB*H2D;i+=NTHR) s2->sh[i] = g_h2[i];
      __syncthreads();
      if (t < 128){
        int g = t>>5, ln = t&31;
        const float* wi = Wih2 + (size_t)(g*H2D+n)*H1D;
        const float* wh = Whh2 + (size_t)(g*H2D+n)*H2D;
        float s[KB], c[KB];
        #pragma unroll
        for (int b=0;b<KB;b++){ s[b]=0.f; c[b]=0.f; }
        #pragma unroll 2
        for (int j=ln;j<H1D;j+=32){
          float w = wi[j];
          #pragma unroll
          for (int b=0;b<KB;b++) kfma(s[b], c[b], w, s2->sx[b*H1D+j]);
        }
        #pragma unroll 2
        for (int j=ln;j<H2D;j+=32){
          float w = wh[j];
          #pragma unroll
          for (int b=0;b<KB;b++) kfma(s[b], c[b], w, s2->sh[b*H2D+j]);
        }
        double bb = (double)bih2[g*H2D+n] + (double)bhh2[g*H2D+n];
        #pragma unroll
        for (int b=0;b<KB;b++){
          float ss=s[b], cc=c[b];
          for (int o=16;o>0;o>>=1){
            ss += __shfl_down_sync(0xffffffffu, ss, o);
            cc += __shfl_down_sync(0xffffffffu, cc, o);
          }
          if (ln==0) s2->sg[g*KB+b] = ((double)ss - (double)cc) + bb;
        }
      }
      __syncthreads();
      if (t<4*KB){
        int gg=t/KB;
        double v = s2->sg[t];
        s2->snl[t] = (gg==2) ? tanh(v) : 1.0/(1.0+exp(-v));
      }
      __syncthreads();
      if (t<KB){
        double cd = s2->snl[1*KB+t]*(double)g_c2[t*H2D+n] + s2->snl[0*KB+t]*s2->snl[2*KB+t];
        float cf = (float)cd;
        g_c2n[t*H2D+n] = cf;
        g_h2n[t*H2D+n] = (float)(s2->snl[3*KB+t]*tanh((double)cf));
      }
    }
    gridbar(ep);

    // ---------- attention: 80 units (beam, 256-token chunk) ----------
    if (bid < NUNITS){
      SM_AT* sa = (SM_AT*)smraw;
      int beam = bid>>3, ch = bid&7;
      if (t<H2D) sa->h2s[t] = g_h2n[beam*H2D+t];
      __syncthreads();
      if (t < 256){
        int qi = t&63, part = t>>6;
        const float* w = Wq + qi*H2D + part*16;
        float s=0.f, c=0.f;
        #pragma unroll
        for (int j=0;j<16;j++) kfma(s, c, w[j], sa->h2s[part*16+j]);
        sa->qp[part][qi] = s - c;
      }
      __syncthreads();
      if (t<QQ) sa->qs[t] = bq[t] + ((sa->qp[0][t]+sa->qp[1][t])+(sa->qp[2][t]+sa->qp[3][t]));
      __syncthreads();
      int tok = ch*CHUNK + (t & 255);
      float e = -1e30f;
      if (t < 256){
        const float4* kr = (const float4*)(enc_key + (size_t)tok*QQ);
        const float4* q4 = (const float4*)sa->qs;
        float s0=0,c0=0,s1=0,c1=0,s2=0,c2=0,s3=0,c3=0;
        #pragma unroll
        for (int j=0;j<16;j++){
          float4 kv = kr[j];
          float4 qv = q4[j];
          kfma(s0,c0,qv.x,kv.x);
          kfma(s1,c1,qv.y,kv.y);
          kfma(s2,c2,qv.z,kv.z);
          kfma(s3,c3,qv.w,kv.w);
        }
        e = ((s0-c0)+(s1-c1))+((s2-c2)+(s3-c3));
      }
      float m = e;
      for (int o=16;o>0;o>>=1) m = fmaxf(m, __shfl_down_sync(0xffffffffu, m, o));
      if (lane==0 && wid<8) sa->redm[wid]=m;
      __syncthreads();
      float M = sa->redm[0];
      #pragma unroll
      for (int q=1;q<8;q++) M = fmaxf(M, sa->redm[q]);
      float wexp=0.f, wmask=0.f;
      if (t < 256){
        wexp = expf(e-M);
        wmask = wexp*mask[tok];
        sa->ws[t] = wmask;
      }
      float a=wexp, b2=wmask;
      for (int o=16;o>0;o>>=1){
        a  += __shfl_down_sync(0xffffffffu, a, o);
        b2 += __shfl_down_sync(0xffffffffu, b2, o);
      }
      if (lane==0 && wid<8){ sa->redab[wid][0]=a; sa->redab[wid][1]=b2; }
      __syncthreads();
      {
        int v = t&63, grp = t>>6;      // 8 groups x 32 tokens, all 512 threads
        const float* vb = enc_val + (size_t)(ch*CHUNK + grp*32)*QQ + v;
        float s0=0,c0=0,s1=0,c1=0;
        #pragma unroll 4
        for (int tl=0; tl<32; tl+=2){
          kfma(s0,c0, sa->ws[grp*32+tl],   vb[(size_t)tl*QQ]);
          kfma(s1,c1, sa->ws[grp*32+tl+1], vb[(size_t)(tl+1)*QQ]);
        }
        sa->cs[grp][v] = (s0-c0)+(s1-c1);
      }
      __syncthreads();
      if (t<QQ){
        float cc = ((sa->cs[0][t]+sa->cs[1][t])+(sa->cs[2][t]+sa->cs[3][t]))
                 + ((sa->cs[4][t]+sa->cs[5][t])+(sa->cs[6][t]+sa->cs[7][t]));
        g_attC[(beam*NCHUNK+ch)*QQ + t] = cc;
      }
      if (t==0){
        g_attM[beam*NCHUNK+ch]=M;
        g_attA[beam*NCHUNK+ch]=((sa->redab[0][0]+sa->redab[1][0])+(sa->redab[2][0]+sa->redab[3][0]))
                              +((sa->redab[4][0]+sa->redab[5][0])+(sa->redab[6][0]+sa->redab[7][0]));
        g_attB[beam*NCHUNK+ch]=((sa->redab[0][1]+sa->redab[1][1])+(sa->redab[2][1]+sa->redab[3][1]))
                              +((sa->redab[4][1]+sa->redab[5][1])+(sa->redab[6][1]+sa->redab[7][1]));
      }
    }
    gridbar(ep);

    // ---------- logits (+merge prologue): all 148 blocks ----------
    {
      SM_LO* so = (SM_LO*)smraw;
      if (t<KB){
        float M=-1e30f;
        #pragma unroll
        for (int c=0;c<NCHUNK;c++) M = fmaxf(M, g_attM[t*NCHUNK+c]);
        so->sM[t]=M;
      }
      __syncthreads();
      if (t<KB*NCHUNK){
        int b=t/NCHUNK;
        so->scf[b][t%NCHUNK] = expf(g_attM[t]-so->sM[b]);
      }
      __syncthreads();
      if (t<KB){
        double A=0.0, B=0.0;
        #pragma unroll
        for (int c=0;c<NCHUNK;c++){
          A += (double)g_attA[t*NCHUNK+c]*(double)so->scf[t][c];
          B += (double)g_attB[t*NCHUNK+c]*(double)so->scf[t][c];
        }
        so->sA[t]=A; so->sB[t]=B;
      }
      __syncthreads();
      for (int i=t;i<KB*128;i+=NTHR){
        int b=i>>7, j=i&127;
        float x;
        if (j < H2D) x = g_h2n[b*H2D+j];
        else {
          int v = j - H2D;
          float s=0.f, c=0.f;
          #pragma unroll
          for (int cc=0;cc<NCHUNK;cc++) kfma(s, c, g_attC[(b*NCHUNK+cc)*QQ+v], so->scf[b][cc]);
          double Cd = (double)s - (double)c;
          x = (float)((Cd/so->sA[b]) / fmax(so->sB[b]/so->sA[b], 2e-30));
          if (bid == 0) g_ctxn[b*QQ+v] = x;
        }
        so->xs[i] = x;
      }
      __syncthreads();
      float ex[KB];
      #pragma unroll
      for (int b=0;b<KB;b++) ex[b]=0.f;
      if (t < LROWS){
        int v0 = bid*RPB + t;
        int v1 = v0 + LROWS;
        bool ok0 = v0 < VV, ok1 = v1 < VV;
        const ulonglong2* wr0 = (const ulonglong2*)(Wc + (size_t)(ok0?v0:0)*128);
        const ulonglong2* wr1 = (const ulonglong2*)(Wc + (size_t)(ok1?v1:0)*128);
        const ulonglong2* xp = (const ulonglong2*)so->xs;
        unsigned long long a0[KB], a1[KB];
        #pragma unroll
        for (int b=0;b<KB;b++){ a0[b]=0ull; a1[b]=0ull; }
        #pragma unroll 2
        for (int j=0;j<32;j++){
          ulonglong2 w0 = wr0[j];
          ulonglong2 w1 = wr1[j];
          #pragma unroll
          for (int b=0;b<KB;b++){
            ulonglong2 xv = xp[b*32+j];
            ffma2(a0[b], w0.x, xv.x);
            ffma2(a0[b], w0.y, xv.y);
            ffma2(a1[b], w1.x, xv.x);
            ffma2(a1[b], w1.y, xv.y);
          }
        }
        float bc0 = ok0 ? bc[v0] : 0.f;
        float bc1 = ok1 ? bc[v1] : 0.f;
        #pragma unroll
        for (int b=0;b<KB;b++){
          float lo0 = __uint_as_float((unsigned)(a0[b] & 0xffffffffu));
          float hi0 = __uint_as_float((unsigned)(a0[b] >> 32));
          float lo1 = __uint_as_float((unsigned)(a1[b] & 0xffffffffu));
          float hi1 = __uint_as_float((unsigned)(a1[b] >> 32));
          float l0 = ok0 ? (lo0 + hi0) + bc0 : -1e30f;
          float l1 = ok1 ? (lo1 + hi1) + bc1 : -1e30f;
          so->lg[b][t]       = l0;
          so->lg[b][t+LROWS] = l1;
          ex[b] = expf(l0) + expf(l1);
        }
      }
      #pragma unroll
      for (int b=0;b<KB;b++){
        float s = ex[b];
        for (int o=16;o>0;o>>=1) s += __shfl_down_sync(0xffffffffu, s, o);
        if (lane==0) so->wred[wid][b] = s;
      }
      __syncthreads();
      if (t<KB){
        double s=0.0;
        for (int w=0;w<16;w++) s += (double)so->wred[w][t];
        g_sump[bid*KB+t] = s;
      }
      if (wid < KB){
        int bm = wid;
        for (int j=0;j<TPB;j++){
          unsigned long long best=0ull;
          for (int r2=lane; r2<RPB; r2+=32){
            unsigned long long k = ((unsigned long long)ordkey(so->lg[bm][r2])<<32) | (unsigned)(~(unsigned)r2);
            if (k>best) best=k;
          }
          for (int o=16;o>0;o>>=1){
            unsigned long long ok = __shfl_down_sync(0xffffffffu, best, o);
            if (ok>best) best=ok;
          }
          best = __shfl_sync(0xffffffffu, best, 0);
          int rs = (int)(~(unsigned)(best & 0xffffffffu));
          if (lane==0){
            g_cand_val[(bid*KB+bm)*TPB+j] = so->lg[bm][rs];
            g_cand_idx[(bid*KB+bm)*TPB+j] = bid*RPB + rs;
            so->lg[bm][rs] = -1e30f;
          }
          __syncwarp();
        }
      }
    }
    gridbar(ep);

    // ---------- select: block 0 ----------
    if (bid==0){
      SM_SE* se = (SM_SE*)smraw;
      {
        double s=0.0;
        if (t < 250){
          int b = t/25, part = t%25;
          for (int b2=part; b2<GRID; b2+=25) s += g_sump[b2*KB+b];
        }
        if (t < 256) se->sp[t]=s;
      }
      __syncthreads();
      if (t<KB){
        double s=0.0;
        for (int q=0;q<25;q++) s += se->sp[t*25+q];
        se->slse[t] = (float)log(s);
        se->sscore[t] = g_scores[t];
        se->sfin[t] = g_fin[t];
      }
      __syncthreads();
      if (t < 256){
        unsigned long long list[10];
        #pragma unroll
        for (int j=0;j<10;j++) list[j]=0ull;
        for (int c=t;c<NCAND;c+=256){
          int b = (c/TPB)%KB;
          if (se->sfin[b]) continue;
          if (step==0 && b>0) continue;
          float logp = g_cand_val[c] - se->slse[b];
          float v = se->sscore[b] + logp;
          int flat = b*VV + g_cand_idx[c];
          unsigned long long k = ((unsigned long long)ordkey(v)<<32) | (unsigned)(~(unsigned)flat);
          if (k > list[9]){
            list[9]=k;
            for (int j=8;j>=0;j--){
              if (list[j] < list[j+1]){ unsigned long long tmp=list[j]; list[j]=list[j+1]; list[j+1]=tmp; }
              else break;
            }
          }
        }
        if (t<KB && se->sfin[t]){
          float v = se->sscore[t];
          int flat = t*VV + EOSTOK;
          unsigned long long k = ((unsigned long long)ordkey(v)<<32) | (unsigned)(~(unsigned)flat);
          if (k > list[9]){
            list[9]=k;
            for (int j=8;j>=0;j--){
              if (list[j] < list[j+1]){ unsigned long long tmp=list[j]; list[j]=list[j+1]; list[j+1]=tmp; }
              else break;
            }
          }
        }
        #pragma unroll
        for (int j=0;j<10;j++) se->skeys[t*10+j]=list[j];
      }
      __syncthreads();
      for (int j=0;j<10;j++){
        unsigned long long m=0ull;
        if (t < 256){
          #pragma unroll
          for (int q=0;q<10;q++){ unsigned long long k=se->skeys[t*10+q]; if (k>m) m=k; }
        }
        for (int o=16;o>0;o>>=1){
          unsigned long long ok = __shfl_down_sync(0xffffffffu, m, o);
          if (ok>m) m=ok;
        }
        if (lane==0) se->wmax[wid]=m;
        __syncthreads();
        if (t==0){
          unsigned long long w=se->wmax[0];
          for (int q=1;q<16;q++) if (se->wmax[q]>w) w=se->wmax[q];
          se->swin=w; se->topk[j]=w;
        }
        __syncthreads();
        unsigned long long win = se->swin;
        if (t < 256){
          #pragma unroll
          for (int q=0;q<10;q++) if (se->skeys[t*10+q]==win) se->skeys[t*10+q]=0ull;
        }
        __syncthreads();
      }
      if (t<KB){
        unsigned long long k = se->topk[t];
        se->sval[t] = unordkey((unsigned)(k>>32));
        int flat = (int)(~(unsigned)(k & 0xffffffffu));
        se->spb[t]  = flat / VV;
        se->stok[t] = flat % VV;
      }
      for (int i=t;i<KB*SEQW;i+=NTHR) se->sseq[i] = g_seqs[i];
      __syncthreads();
      for (int i=t;i<KB*H1D;i+=NTHR){
        int nb=i>>7, u=i&127;
        g_h1[i]=g_h1n[se->spb[nb]*H1D+u];
        g_c1[i]=g_c1n[se->spb[nb]*H1D+u];
      }
      for (int i=t;i<KB*H2D;i+=NTHR){
        int nb=i>>6, u=i&63;
        g_h2[i]=g_h2n[se->spb[nb]*H2D+u];
        g_c2[i]=g_c2n[se->spb[nb]*H2D+u];
        g_ctx[i]=g_ctxn[se->spb[nb]*QQ+u];
      }
      for (int i=t;i<KB*SEQW;i+=NTHR){
        int nb=i/SEQW, cc=i%SEQW;
        g_seqs[i] = se->sseq[se->spb[nb]*SEQW+cc];
      }
      __syncthreads();
      if (t<KB){
        g_seqs[t*SEQW + step + 1] = se->stok[t];
        g_prev[t]   = se->stok[t];
        g_scores[t] = se->sval[t];
        g_fin[t]    = se->sfin[se->spb[t]] | (se->stok[t]==EOSTOK);
      }
    }
    gridbar(ep);
  }

  // ---------- finalize: block 0 ----------
  if (bid==0){
    SM_SE* se = (SM_SE*)smraw;
    if (t<KB){
      int first=-1;
      for (int c=1;c<=MAXLEN;c++){
        if (g_seqs[t*SEQW+c]==EOSTOK){ first=c-1; break; }
      }
      float len = (first>=0) ? (float)(first+2) : (float)(MAXLEN+2);
      se->sval[t] = (float)((double)g_scores[t] / pow((double)len, 1.2));
    }
    __syncthreads();
    for (int i=t;i<KB*SEQW;i+=NTHR) out[i] = (float)g_seqs[i];
    if (t<KB){
      out[KB*SEQW + t]       = g_scores[t];
      out[KB*SEQW + KB + t]  = se->sval[t];
    }
  }
}

extern "C" void kernel_launch(void* const* d_in, const int* in_sizes, int n_in,
                              void* d_out, int out_size){
  const float* enc_key = (const float*)d_in[0];
  const float* enc_val = (const float*)d_in[1];
  const float* mask    = (const float*)d_in[2];
  const float* emb     = (const float*)d_in[3];
  const float* Wih1    = (const float*)d_in[4];
  const float* Whh1    = (const float*)d_in[5];
  const float* bih1    = (const float*)d_in[6];
  const float* bhh1    = (const float*)d_in[7];
  const float* Wih2    = (const float*)d_in[8];
  const float* Whh2    = (const float*)d_in[9];
  const float* bih2    = (const float*)d_in[10];
  const float* bhh2    = (const float*)d_in[11];
  const float* Wq      = (const float*)d_in[12];
  const float* bq      = (const float*)d_in[13];
  const float* Wc      = (const float*)d_in[14];
  const float* bc      = (const float*)d_in[15];

  mega_kernel<<<GRID,NTHR>>>(enc_key, enc_val, mask, emb,
                             Wih1, Whh1, bih1, bhh1,
                             Wih2, Whh2, bih2, bhh2,
                             Wq, bq, Wc, bc, (float*)d_out);
}